// round 6
// baseline (speedup 1.0000x reference)
#include <cuda_runtime.h>
#include <cuda_bf16.h>
#include <cstdint>
#include <cstddef>
#include <math.h>

// Problem constants
#define B_   2
#define S_   2048
#define HID_ 2048
#define NH_  16
#define HD_  128
#define M_   (B_ * S_)     // 4096
#define K_   HID_          // 2048
#define KEX_ (3 * K_)      // 6144 expanded (hi|lo|hi split)

// ---------------------------------------------------------------------------
// Scratch (allocation-free rule: __device__ globals)
// ---------------------------------------------------------------------------
__device__ float g_q[B_ * NH_ * S_ * HD_];     // [b,h,s,d] fp32
__device__ float g_k[B_ * NH_ * S_ * HD_];
__device__ float g_v[B_ * NH_ * S_ * HD_];
__device__ float g_ctx[B_ * S_ * HID_];        // [b,s,h*HD+d] fp32

__device__ __nv_bfloat16 g_aex[(size_t)M_ * KEX_];     // hs  expanded
__device__ __nv_bfloat16 g_cex[(size_t)M_ * KEX_];     // ctx expanded
__device__ __nv_bfloat16 g_wqe[(size_t)HID_ * KEX_];   // weights expanded
__device__ __nv_bfloat16 g_wke[(size_t)HID_ * KEX_];
__device__ __nv_bfloat16 g_wve[(size_t)HID_ * KEX_];
__device__ __nv_bfloat16 g_woe[(size_t)HID_ * KEX_];

// ---------------------------------------------------------------------------
// fp32 -> bf16 hi/lo split, expanded-K layout (vectorized: 4 elems/thread).
// mode 0 ("A" side):  [hi | lo | hi]
// mode 1 ("W" side):  [hi | hi | lo]
// A'·W'^T over Kex = Ah·Wh + Al·Wh + Ah·Wl  (exact to ~2^-18).
// ---------------------------------------------------------------------------
__global__ void split_expand(const float* __restrict__ X,
                             __nv_bfloat16* __restrict__ Y,
                             int total4, int mode)
{
    const int t = blockIdx.x * blockDim.x + threadIdx.x;
    if (t >= total4) return;
    const int idx = t * 4;
    const int r = idx >> 11;           // / 2048
    const int k = idx & (K_ - 1);
    const float4 x = *(const float4*)(X + idx);

    __nv_bfloat16 hi[4], lo[4];
    const float xs[4] = {x.x, x.y, x.z, x.w};
#pragma unroll
    for (int i = 0; i < 4; i++) {
        hi[i] = __float2bfloat16_rn(xs[i]);
        lo[i] = __float2bfloat16_rn(xs[i] - __bfloat162float(hi[i]));
    }
    __nv_bfloat16* dst = Y + (size_t)r * KEX_ + k;
    *(uint2*)(dst) = *(const uint2*)hi;
    if (mode == 0) {
        *(uint2*)(dst + K_)     = *(const uint2*)lo;
        *(uint2*)(dst + 2 * K_) = *(const uint2*)hi;
    } else {
        *(uint2*)(dst + K_)     = *(const uint2*)hi;
        *(uint2*)(dst + 2 * K_) = *(const uint2*)lo;
    }
}

// ---------------------------------------------------------------------------
// bf16 mma.sync GEMM:  C[M,N] = A'[M,Kex] · W'[N,Kex]^T   (fp32 accumulate)
// CTA tile 128x128x64, 4 warps (2m x 2n), warp tile 64x64 (4 m16 x 8 n8).
// 3-stage cp.async pipeline; dynamic smem 108KB; 2 CTAs/SM.
// smem rows padded to 72 bf16 (144B) -> conflict-free ldmatrix.
// layout 0: C[m*N+n]; layout 1: scatter to [b,h,s,d].
// ---------------------------------------------------------------------------
#define GBM 128
#define GBN 128
#define GBK 64
#define LDP 72                        // padded smem row length (bf16)
#define GSTG 3                        // pipeline stages
#define STG_B (GBM * LDP * 2)         // 18432 bytes per matrix per stage
#define GEMM_SMEM (2 * GSTG * STG_B)  // 110592

__device__ __forceinline__ void cpasync16(unsigned int smem_dst, const void* gsrc) {
    asm volatile("cp.async.cg.shared.global [%0], [%1], 16;\n" :: "r"(smem_dst), "l"(gsrc));
}
__device__ __forceinline__ void cp_commit() {
    asm volatile("cp.async.commit_group;\n");
}

__device__ __forceinline__ void ldm_x4(unsigned int& r0, unsigned int& r1,
                                       unsigned int& r2, unsigned int& r3,
                                       unsigned int addr) {
    asm volatile("ldmatrix.sync.aligned.m8n8.x4.shared.b16 {%0,%1,%2,%3}, [%4];\n"
                 : "=r"(r0), "=r"(r1), "=r"(r2), "=r"(r3) : "r"(addr));
}

__device__ __forceinline__ void mma_bf16(float* c, const unsigned int* a,
                                         const unsigned int* b) {
    asm volatile(
        "mma.sync.aligned.m16n8k16.row.col.f32.bf16.bf16.f32 "
        "{%0,%1,%2,%3}, {%4,%5,%6,%7}, {%8,%9}, {%0,%1,%2,%3};\n"
        : "+f"(c[0]), "+f"(c[1]), "+f"(c[2]), "+f"(c[3])
        : "r"(a[0]), "r"(a[1]), "r"(a[2]), "r"(a[3]), "r"(b[0]), "r"(b[1]));
}

__global__ __launch_bounds__(128, 2)
void gemm_bf16(const __nv_bfloat16* __restrict__ A,
               const __nv_bfloat16* __restrict__ W,
               float* __restrict__ C, int N, int Kex, int layout)
{
    extern __shared__ char gsm[];
    const unsigned int sbase = (unsigned int)__cvta_generic_to_shared(gsm);
    const unsigned int sBoff = GSTG * STG_B;   // B region after 3 A stages

    const int tid  = threadIdx.x;
    const int lane = tid & 31;
    const int w    = tid >> 5;            // 0..3
    const int wm   = (w >> 1) << 6;       // 0 or 64
    const int wn   = (w & 1) << 6;        // 0 or 64
    const int m0   = blockIdx.y * GBM;
    const int n0   = blockIdx.x * GBN;

    float acc[4][8][4];
#pragma unroll
    for (int mi = 0; mi < 4; mi++)
#pragma unroll
        for (int ni = 0; ni < 8; ni++)
#pragma unroll
            for (int e = 0; e < 4; e++) acc[mi][ni][e] = 0.0f;

    // load mapping: 128 rows x 8 chunks(16B) per matrix; 128 threads x 8 iters
    const int lr = tid >> 3;      // 0..15
    const int lc = tid & 7;       // 16B chunk

    const int NT = Kex / GBK;     // 96

    auto load_stage = [&](int kt, int s) {
        const unsigned int aD = sbase + s * STG_B;
        const unsigned int bD = sbase + sBoff + s * STG_B;
        const __nv_bfloat16* Ap = A + (size_t)m0 * Kex + kt * GBK + lc * 8;
        const __nv_bfloat16* Wp = W + (size_t)n0 * Kex + kt * GBK + lc * 8;
#pragma unroll
        for (int i = 0; i < 8; i++) {
            const int row = lr + i * 16;
            const unsigned int off = (unsigned int)(row * LDP + lc * 8) * 2;
            cpasync16(aD + off, Ap + (size_t)row * Kex);
            cpasync16(bD + off, Wp + (size_t)row * Kex);
        }
        cp_commit();
    };

    load_stage(0, 0);
    load_stage(1, 1);

    for (int kt = 0; kt < NT; kt++) {
        if (kt + 1 < NT) {
            asm volatile("cp.async.wait_group 1;\n");
        } else {
            asm volatile("cp.async.wait_group 0;\n");
        }
        __syncthreads();

        if (kt + 2 < NT) load_stage(kt + 2, (kt + 2) % GSTG);

        const int s = kt % GSTG;
        const unsigned int aBase = sbase + s * STG_B;
        const unsigned int bBase = sbase + sBoff + s * STG_B;

#pragma unroll
        for (int ks = 0; ks < 4; ks++) {
            unsigned int afr[4][4], bfr[8][2];
#pragma unroll
            for (int mi = 0; mi < 4; mi++) {
                const int row = wm + mi * 16 + (lane & 15);
                const unsigned int addr =
                    aBase + (unsigned int)(row * LDP + ks * 16 + (lane >> 4) * 8) * 2;
                ldm_x4(afr[mi][0], afr[mi][1], afr[mi][2], afr[mi][3], addr);
            }
#pragma unroll
            for (int p = 0; p < 4; p++) {
                const int nrow = wn + p * 16 + (lane & 7) + ((lane >> 4) << 3);
                const int chunk = (lane >> 3) & 1;
                const unsigned int addr =
                    bBase + (unsigned int)(nrow * LDP + ks * 16 + chunk * 8) * 2;
                ldm_x4(bfr[2 * p][0], bfr[2 * p][1], bfr[2 * p + 1][0], bfr[2 * p + 1][1], addr);
            }
#pragma unroll
            for (int mi = 0; mi < 4; mi++)
#pragma unroll
                for (int ni = 0; ni < 8; ni++)
                    mma_bf16(acc[mi][ni], afr[mi], bfr[ni]);
        }
    }

    // epilogue
#pragma unroll
    for (int mi = 0; mi < 4; mi++) {
#pragma unroll
        for (int ni = 0; ni < 8; ni++) {
            const int rr = m0 + wm + mi * 16 + (lane >> 2);
            const int cc = n0 + wn + ni * 8 + ((lane & 3) << 1);
#pragma unroll
            for (int e = 0; e < 4; e++) {
                const int m = rr + ((e >> 1) << 3);   // +8 for e=2,3
                const int n = cc + (e & 1);
                if (layout == 0) {
                    C[(size_t)m * N + n] = acc[mi][ni][e];
                } else {
                    const int b = m >> 11, s = m & (S_ - 1);
                    const int h = n >> 7,  d = n & (HD_ - 1);
                    C[(((size_t)(b * NH_ + h)) * S_ + s) * HD_ + d] = acc[mi][ni][e];
                }
            }
        }
    }
}

// ---------------------------------------------------------------------------
// RoPE in place on g_q / g_k ([b,h,s,d]).
// ---------------------------------------------------------------------------
__global__ void rope_kernel(float* __restrict__ q, float* __restrict__ k,
                            const int* __restrict__ pos_ids)
{
    const int idx = blockIdx.x * blockDim.x + threadIdx.x;
    const int total = B_ * NH_ * S_ * (HD_ / 2);
    if (idx >= total) return;
    const int d = idx & 63;
    int t = idx >> 6;
    const int s = t & (S_ - 1);
    t >>= 11;
    const int h = t & (NH_ - 1);
    const int b = t >> 4;

    const int p = pos_ids[b * S_ + s];
    const float e = (float)(-(2 * d)) * 0.10381025296523008f;
    const float inv_f = exp2f(e);
    const float ang = (float)p * inv_f;
    float sn, cs;
    sincosf(ang, &sn, &cs);

    const size_t base = (((size_t)(b * NH_ + h)) * S_ + s) * HD_ + d;
    const float q1 = q[base], q2 = q[base + 64];
    q[base]      = q1 * cs - q2 * sn;
    q[base + 64] = q2 * cs + q1 * sn;
    const float k1 = k[base], k2 = k[base + 64];
    k[base]      = k1 * cs - k2 * sn;
    k[base + 64] = k2 * cs + k1 * sn;
}

// ---------------------------------------------------------------------------
// Flash attention (fp32, causal) — unchanged (known good).
// ---------------------------------------------------------------------------
#define FTILE 64
#define KTS_STRIDE 68

__global__ __launch_bounds__(256, 1)
void flash_attn(const float* __restrict__ Qg, const float* __restrict__ Kg,
                const float* __restrict__ Vg, float* __restrict__ ctx)
{
    extern __shared__ float sm[];
    float* Qs  = sm;
    float* Kts = Qs + 64 * 128;
    float* Vs  = Kts + 128 * KTS_STRIDE;
    float* Ps  = Vs + 64 * 128;

    const int tid = threadIdx.x;
    const int tx = tid & 15;
    const int ty = tid >> 4;
    const int qt = blockIdx.x;
    const int bh = blockIdx.y;
    const size_t base = (size_t)bh * S_ * HD_;
    const float* Qp = Qg + base + (size_t)qt * FTILE * HD_;

    for (int i = tid; i < FTILE * 32; i += 256) {
        const int r = i >> 5, c4 = (i & 31) << 2;
        *(float4*)&Qs[r * 128 + c4] = *(const float4*)&Qp[(size_t)r * HD_ + c4];
    }

    float m_i[4], l_i[4], acc[4][8];
#pragma unroll
    for (int r = 0; r < 4; r++) {
        m_i[r] = -3.0e30f;
        l_i[r] = 0.0f;
#pragma unroll
        for (int c = 0; c < 8; c++) acc[r][c] = 0.0f;
    }

    const float SCALE = 0.08838834764831845f;

    for (int j = 0; j <= qt; j++) {
        __syncthreads();
        const float* Kp = Kg + base + (size_t)j * FTILE * HD_;
        const float* Vp = Vg + base + (size_t)j * FTILE * HD_;
        for (int i = tid; i < FTILE * 32; i += 256) {
            const int r = i >> 5, c4 = (i & 31) << 2;
            const float4 kv = *(const float4*)&Kp[(size_t)r * HD_ + c4];
            Kts[(c4 + 0) * KTS_STRIDE + r] = kv.x;
            Kts[(c4 + 1) * KTS_STRIDE + r] = kv.y;
            Kts[(c4 + 2) * KTS_STRIDE + r] = kv.z;
            Kts[(c4 + 3) * KTS_STRIDE + r] = kv.w;
            *(float4*)&Vs[r * 128 + c4] = *(const float4*)&Vp[(size_t)r * HD_ + c4];
        }
        __syncthreads();

        float sreg[4][4];
#pragma unroll
        for (int r = 0; r < 4; r++)
#pragma unroll
            for (int c = 0; c < 4; c++) sreg[r][c] = 0.0f;

#pragma unroll 4
        for (int kk = 0; kk < HD_; kk++) {
            const float4 kv = *(const float4*)&Kts[kk * KTS_STRIDE + tx * 4];
            float qv[4];
#pragma unroll
            for (int r = 0; r < 4; r++) qv[r] = Qs[(ty * 4 + r) * 128 + kk];
#pragma unroll
            for (int r = 0; r < 4; r++) {
                sreg[r][0] = fmaf(qv[r], kv.x, sreg[r][0]);
                sreg[r][1] = fmaf(qv[r], kv.y, sreg[r][1]);
                sreg[r][2] = fmaf(qv[r], kv.z, sreg[r][2]);
                sreg[r][3] = fmaf(qv[r], kv.w, sreg[r][3]);
            }
        }

        const bool diag = (j == qt);
#pragma unroll
        for (int r = 0; r < 4; r++) {
            const int qrow = qt * FTILE + ty * 4 + r;
#pragma unroll
            for (int c = 0; c < 4; c++) {
                sreg[r][c] *= SCALE;
                if (diag) {
                    const int kcol = j * FTILE + tx * 4 + c;
                    if (kcol > qrow) sreg[r][c] = -1.0e30f;
                }
            }
        }

#pragma unroll
        for (int r = 0; r < 4; r++) {
            float mloc = fmaxf(fmaxf(sreg[r][0], sreg[r][1]),
                               fmaxf(sreg[r][2], sreg[r][3]));
#pragma unroll
            for (int off = 8; off > 0; off >>= 1)
                mloc = fmaxf(mloc, __shfl_xor_sync(0xffffffffu, mloc, off, 16));
            const float mnew = fmaxf(m_i[r], mloc);
            const float corr = __expf(m_i[r] - mnew);
            float p[4], lloc = 0.0f;
#pragma unroll
            for (int c = 0; c < 4; c++) {
                p[c] = __expf(sreg[r][c] - mnew);
                lloc += p[c];
            }
#pragma unroll
            for (int off = 8; off > 0; off >>= 1)
                lloc += __shfl_xor_sync(0xffffffffu, lloc, off, 16);
            l_i[r] = l_i[r] * corr + lloc;
            m_i[r] = mnew;
#pragma unroll
            for (int c = 0; c < 8; c++) acc[r][c] *= corr;
#pragma unroll
            for (int c = 0; c < 4; c++)
                Ps[(ty * 4 + r) * FTILE + tx * 4 + c] = p[c];
        }
        __syncthreads();

#pragma unroll 4
        for (int c = 0; c < FTILE; c++) {
            const float4 v0 = *(const float4*)&Vs[c * 128 + tx * 8];
            const float4 v1 = *(const float4*)&Vs[c * 128 + tx * 8 + 4];
#pragma unroll
            for (int r = 0; r < 4; r++) {
                const float pv = Ps[(ty * 4 + r) * FTILE + c];
                acc[r][0] = fmaf(pv, v0.x, acc[r][0]);
                acc[r][1] = fmaf(pv, v0.y, acc[r][1]);
                acc[r][2] = fmaf(pv, v0.z, acc[r][2]);
                acc[r][3] = fmaf(pv, v0.w, acc[r][3]);
                acc[r][4] = fmaf(pv, v1.x, acc[r][4]);
                acc[r][5] = fmaf(pv, v1.y, acc[r][5]);
                acc[r][6] = fmaf(pv, v1.z, acc[r][6]);
                acc[r][7] = fmaf(pv, v1.w, acc[r][7]);
            }
        }
    }

    const int b = bh >> 4;
    const int h = bh & (NH_ - 1);
#pragma unroll
    for (int r = 0; r < 4; r++) {
        const float inv = 1.0f / l_i[r];
        const int srow = qt * FTILE + ty * 4 + r;
        float* dst = ctx + (((size_t)(b * S_ + srow)) * NH_ + h) * HD_ + tx * 8;
#pragma unroll
        for (int c = 0; c < 8; c++) dst[c] = acc[r][c] * inv;
    }
}

// ---------------------------------------------------------------------------
extern "C" void kernel_launch(void* const* d_in, const int* in_sizes, int n_in,
                              void* d_out, int out_size)
{
    const float* hs  = (const float*)d_in[0];
    // d_in[1] = attention_mask: deterministically causal, applied analytically
    const int*   pos = (const int*)d_in[2];
    const float* Wq  = (const float*)d_in[3];
    const float* Wk  = (const float*)d_in[4];
    const float* Wv  = (const float*)d_in[5];
    const float* Wo  = (const float*)d_in[6];
    float* out = (float*)d_out;

    float *q, *k, *v, *ctx;
    __nv_bfloat16 *aex, *cex, *wqe, *wke, *wve, *woe;
    cudaGetSymbolAddress((void**)&q,   g_q);
    cudaGetSymbolAddress((void**)&k,   g_k);
    cudaGetSymbolAddress((void**)&v,   g_v);
    cudaGetSymbolAddress((void**)&ctx, g_ctx);
    cudaGetSymbolAddress((void**)&aex, g_aex);
    cudaGetSymbolAddress((void**)&cex, g_cex);
    cudaGetSymbolAddress((void**)&wqe, g_wqe);
    cudaGetSymbolAddress((void**)&wke, g_wke);
    cudaGetSymbolAddress((void**)&wve, g_wve);
    cudaGetSymbolAddress((void**)&woe, g_woe);

    const int nA4 = (M_ * K_) / 4;
    const int nW4 = (HID_ * K_) / 4;
    split_expand<<<(nA4 + 255) / 256, 256>>>(hs, aex, nA4, 0);
    split_expand<<<(nW4 + 255) / 256, 256>>>(Wq, wqe, nW4, 1);
    split_expand<<<(nW4 + 255) / 256, 256>>>(Wk, wke, nW4, 1);
    split_expand<<<(nW4 + 255) / 256, 256>>>(Wv, wve, nW4, 1);
    split_expand<<<(nW4 + 255) / 256, 256>>>(Wo, woe, nW4, 1);

    static bool attr_set = false;
    const int fsmem = (64 * 128 + 128 * KTS_STRIDE + 64 * 128 + 64 * 64) * sizeof(float);
    if (!attr_set) {
        cudaFuncSetAttribute(gemm_bf16, cudaFuncAttributeMaxDynamicSharedMemorySize, GEMM_SMEM);
        cudaFuncSetAttribute(flash_attn, cudaFuncAttributeMaxDynamicSharedMemorySize, fsmem);
        attr_set = true;
    }

    const dim3 ggrid(HID_ / GBN, M_ / GBM);   // (16, 32)
    gemm_bf16<<<ggrid, 128, GEMM_SMEM>>>(aex, wqe, q, HID_, KEX_, 1);
    gemm_bf16<<<ggrid, 128, GEMM_SMEM>>>(aex, wke, k, HID_, KEX_, 1);
    gemm_bf16<<<ggrid, 128, GEMM_SMEM>>>(aex, wve, v, HID_, KEX_, 1);

    const int rope_total = B_ * NH_ * S_ * (HD_ / 2);
    rope_kernel<<<(rope_total + 255) / 256, 256>>>(q, k, pos);

    flash_attn<<<dim3(S_ / FTILE, B_ * NH_), 256, fsmem>>>(q, k, v, ctx);

    split_expand<<<(nA4 + 255) / 256, 256>>>(ctx, cex, nA4, 0);
    gemm_bf16<<<ggrid, 128, GEMM_SMEM>>>(cex, woe, out, HID_, KEX_, 0);
}

// round 7
// speedup vs baseline: 1.8263x; 1.8263x over previous
#include <cuda_runtime.h>
#include <cuda_bf16.h>
#include <cstdint>
#include <cstddef>
#include <math.h>

// Problem constants
#define B_   2
#define S_   2048
#define HID_ 2048
#define NH_  16
#define HD_  128
#define M_   (B_ * S_)     // 4096
#define K_   HID_          // 2048
#define KEX_ (3 * K_)      // 6144 expanded (hi|lo|hi split)

// ---------------------------------------------------------------------------
// Scratch (allocation-free rule: __device__ globals)
// ---------------------------------------------------------------------------
__device__ float g_q[B_ * NH_ * S_ * HD_];     // [b,h,s,d] fp32
__device__ float g_k[B_ * NH_ * S_ * HD_];
__device__ float g_v[B_ * NH_ * S_ * HD_];
__device__ float g_ctx[B_ * S_ * HID_];        // [b,s,h*HD+d] fp32

__device__ __nv_bfloat16 g_aex[(size_t)M_ * KEX_];
__device__ __nv_bfloat16 g_cex[(size_t)M_ * KEX_];
__device__ __nv_bfloat16 g_wqe[(size_t)HID_ * KEX_];
__device__ __nv_bfloat16 g_wke[(size_t)HID_ * KEX_];
__device__ __nv_bfloat16 g_wve[(size_t)HID_ * KEX_];
__device__ __nv_bfloat16 g_woe[(size_t)HID_ * KEX_];

// flash operands: hi/lo bf16
__device__ __nv_bfloat16 g_qh[B_ * NH_ * S_ * HD_];   // [b,h,s,d]
__device__ __nv_bfloat16 g_ql[B_ * NH_ * S_ * HD_];
__device__ __nv_bfloat16 g_kh[B_ * NH_ * S_ * HD_];
__device__ __nv_bfloat16 g_kl[B_ * NH_ * S_ * HD_];
__device__ __nv_bfloat16 g_vth[B_ * NH_ * S_ * HD_];  // [b,h,d,s] (transposed)
__device__ __nv_bfloat16 g_vtl[B_ * NH_ * S_ * HD_];

// ---------------------------------------------------------------------------
// fp32 -> bf16 hi/lo split, expanded-K layout (vectorized).
// ---------------------------------------------------------------------------
__global__ void split_expand(const float* __restrict__ X,
                             __nv_bfloat16* __restrict__ Y,
                             int total4, int mode)
{
    const int t = blockIdx.x * blockDim.x + threadIdx.x;
    if (t >= total4) return;
    const int idx = t * 4;
    const int r = idx >> 11;
    const int k = idx & (K_ - 1);
    const float4 x = *(const float4*)(X + idx);

    __nv_bfloat16 hi[4], lo[4];
    const float xs[4] = {x.x, x.y, x.z, x.w};
#pragma unroll
    for (int i = 0; i < 4; i++) {
        hi[i] = __float2bfloat16_rn(xs[i]);
        lo[i] = __float2bfloat16_rn(xs[i] - __bfloat162float(hi[i]));
    }
    __nv_bfloat16* dst = Y + (size_t)r * KEX_ + k;
    *(uint2*)(dst) = *(const uint2*)hi;
    if (mode == 0) {
        *(uint2*)(dst + K_)     = *(const uint2*)lo;
        *(uint2*)(dst + 2 * K_) = *(const uint2*)hi;
    } else {
        *(uint2*)(dst + K_)     = *(const uint2*)hi;
        *(uint2*)(dst + 2 * K_) = *(const uint2*)lo;
    }
}

// ---------------------------------------------------------------------------
// mma / cp.async helpers
// ---------------------------------------------------------------------------
__device__ __forceinline__ void cpasync16(unsigned int smem_dst, const void* gsrc) {
    asm volatile("cp.async.cg.shared.global [%0], [%1], 16;\n" :: "r"(smem_dst), "l"(gsrc));
}
__device__ __forceinline__ void cp_commit() {
    asm volatile("cp.async.commit_group;\n");
}
__device__ __forceinline__ void ldm_x4(unsigned int& r0, unsigned int& r1,
                                       unsigned int& r2, unsigned int& r3,
                                       unsigned int addr) {
    asm volatile("ldmatrix.sync.aligned.m8n8.x4.shared.b16 {%0,%1,%2,%3}, [%4];\n"
                 : "=r"(r0), "=r"(r1), "=r"(r2), "=r"(r3) : "r"(addr));
}
__device__ __forceinline__ void mma_bf16(float* c, const unsigned int* a,
                                         const unsigned int* b) {
    asm volatile(
        "mma.sync.aligned.m16n8k16.row.col.f32.bf16.bf16.f32 "
        "{%0,%1,%2,%3}, {%4,%5,%6,%7}, {%8,%9}, {%0,%1,%2,%3};\n"
        : "+f"(c[0]), "+f"(c[1]), "+f"(c[2]), "+f"(c[3])
        : "r"(a[0]), "r"(a[1]), "r"(a[2]), "r"(a[3]), "r"(b[0]), "r"(b[1]));
}

// ---------------------------------------------------------------------------
// bf16 mma.sync GEMM — exact R5 configuration (proven 2979us total).
// Tiles 128x128x64, 8 warps (4m x 2n), warp tile 32x64. 3-stage pipeline.
// ---------------------------------------------------------------------------
#define GBM 128
#define GBN 128
#define GBK 64
#define LDP 72
#define GSTG 3
#define STG_B (GBM * LDP * 2)
#define GEMM_SMEM (2 * GSTG * STG_B)

__global__ __launch_bounds__(256, 2)
void gemm_bf16(const __nv_bfloat16* __restrict__ A,
               const __nv_bfloat16* __restrict__ W,
               float* __restrict__ C, int N, int Kex, int layout)
{
    extern __shared__ char gsm[];
    const unsigned int sbase = (unsigned int)__cvta_generic_to_shared(gsm);
    const unsigned int sBoff = GSTG * STG_B;

    const int tid  = threadIdx.x;
    const int lane = tid & 31;
    const int w    = tid >> 5;
    const int wm   = (w >> 1) << 5;
    const int wn   = (w & 1) << 6;
    const int m0   = blockIdx.y * GBM;
    const int n0   = blockIdx.x * GBN;

    float acc[2][8][4];
#pragma unroll
    for (int mi = 0; mi < 2; mi++)
#pragma unroll
        for (int ni = 0; ni < 8; ni++)
#pragma unroll
            for (int e = 0; e < 4; e++) acc[mi][ni][e] = 0.0f;

    const int lr = tid >> 3;
    const int lc = tid & 7;
    const int NT = Kex / GBK;

    auto load_stage = [&](int kt, int s) {
        const unsigned int aD = sbase + s * STG_B;
        const unsigned int bD = sbase + sBoff + s * STG_B;
        const __nv_bfloat16* Ap = A + (size_t)m0 * Kex + kt * GBK + lc * 8;
        const __nv_bfloat16* Wp = W + (size_t)n0 * Kex + kt * GBK + lc * 8;
#pragma unroll
        for (int i = 0; i < 4; i++) {
            const int row = lr + i * 32;
            const unsigned int off = (unsigned int)(row * LDP + lc * 8) * 2;
            cpasync16(aD + off, Ap + (size_t)row * Kex);
            cpasync16(bD + off, Wp + (size_t)row * Kex);
        }
        cp_commit();
    };

    load_stage(0, 0);
    load_stage(1, 1);

    for (int kt = 0; kt < NT; kt++) {
        if (kt + 1 < NT) {
            asm volatile("cp.async.wait_group 1;\n");
        } else {
            asm volatile("cp.async.wait_group 0;\n");
        }
        __syncthreads();

        if (kt + 2 < NT) load_stage(kt + 2, (kt + 2) % GSTG);

        const int s = kt % GSTG;
        const unsigned int aBase = sbase + s * STG_B;
        const unsigned int bBase = sbase + sBoff + s * STG_B;

#pragma unroll
        for (int ks = 0; ks < 4; ks++) {
            unsigned int afr[2][4], bfr[8][2];
#pragma unroll
            for (int mi = 0; mi < 2; mi++) {
                const int row = wm + mi * 16 + (lane & 15);
                const unsigned int addr =
                    aBase + (unsigned int)(row * LDP + ks * 16 + (lane >> 4) * 8) * 2;
                ldm_x4(afr[mi][0], afr[mi][1], afr[mi][2], afr[mi][3], addr);
            }
#pragma unroll
            for (int p = 0; p < 4; p++) {
                const int nrow = wn + p * 16 + (lane & 7) + ((lane >> 4) << 3);
                const int chunk = (lane >> 3) & 1;
                const unsigned int addr =
                    bBase + (unsigned int)(nrow * LDP + ks * 16 + chunk * 8) * 2;
                ldm_x4(bfr[2 * p][0], bfr[2 * p][1], bfr[2 * p + 1][0], bfr[2 * p + 1][1], addr);
            }
#pragma unroll
            for (int mi = 0; mi < 2; mi++)
#pragma unroll
                for (int ni = 0; ni < 8; ni++)
                    mma_bf16(acc[mi][ni], afr[mi], bfr[ni]);
        }
    }

#pragma unroll
    for (int mi = 0; mi < 2; mi++) {
#pragma unroll
        for (int ni = 0; ni < 8; ni++) {
            const int rr = m0 + wm + mi * 16 + (lane >> 2);
            const int cc = n0 + wn + ni * 8 + ((lane & 3) << 1);
#pragma unroll
            for (int e = 0; e < 4; e++) {
                const int m = rr + ((e >> 1) << 3);
                const int n = cc + (e & 1);
                if (layout == 0) {
                    C[(size_t)m * N + n] = acc[mi][ni][e];
                } else {
                    const int b = m >> 11, s2 = m & (S_ - 1);
                    const int h = n >> 7,  d = n & (HD_ - 1);
                    C[(((size_t)(b * NH_ + h)) * S_ + s2) * HD_ + d] = acc[mi][ni][e];
                }
            }
        }
    }
}

// ---------------------------------------------------------------------------
// RoPE + hi/lo split:  fp32 q,k -> qh/ql/kh/kl bf16 ([b,h,s,d]).
// ---------------------------------------------------------------------------
__global__ void rope_split(const float* __restrict__ q, const float* __restrict__ k,
                           const int* __restrict__ pos_ids,
                           __nv_bfloat16* __restrict__ qh, __nv_bfloat16* __restrict__ ql,
                           __nv_bfloat16* __restrict__ kh, __nv_bfloat16* __restrict__ kl)
{
    const int idx = blockIdx.x * blockDim.x + threadIdx.x;
    const int total = B_ * NH_ * S_ * (HD_ / 2);
    if (idx >= total) return;
    const int d = idx & 63;
    int t = idx >> 6;
    const int s = t & (S_ - 1);
    t >>= 11;
    const int h = t & (NH_ - 1);
    const int b = t >> 4;

    const int p = pos_ids[b * S_ + s];
    const float e = (float)(-(2 * d)) * 0.10381025296523008f;
    const float inv_f = exp2f(e);
    const float ang = (float)p * inv_f;
    float sn, cs;
    sincosf(ang, &sn, &cs);

    const size_t base = (((size_t)(b * NH_ + h)) * S_ + s) * HD_ + d;
    const float q1 = q[base], q2 = q[base + 64];
    const float k1 = k[base], k2 = k[base + 64];
    const float rq1 = q1 * cs - q2 * sn, rq2 = q2 * cs + q1 * sn;
    const float rk1 = k1 * cs - k2 * sn, rk2 = k2 * cs + k1 * sn;

    __nv_bfloat16 hv;
    hv = __float2bfloat16_rn(rq1); qh[base]    = hv; ql[base]    = __float2bfloat16_rn(rq1 - __bfloat162float(hv));
    hv = __float2bfloat16_rn(rq2); qh[base+64] = hv; ql[base+64] = __float2bfloat16_rn(rq2 - __bfloat162float(hv));
    hv = __float2bfloat16_rn(rk1); kh[base]    = hv; kl[base]    = __float2bfloat16_rn(rk1 - __bfloat162float(hv));
    hv = __float2bfloat16_rn(rk2); kh[base+64] = hv; kl[base+64] = __float2bfloat16_rn(rk2 - __bfloat162float(hv));
}

// ---------------------------------------------------------------------------
// V transpose + split: g_v [bh][s][d] fp32 -> vth/vtl [bh][d][s] bf16.
// 32x32 smem tile transpose, coalesced both sides.
// ---------------------------------------------------------------------------
__global__ void vsplit_t(const float* __restrict__ v,
                         __nv_bfloat16* __restrict__ vth,
                         __nv_bfloat16* __restrict__ vtl)
{
    __shared__ float tile[32][33];
    const int bh = blockIdx.z;
    const int s0 = blockIdx.x * 32;
    const int d0 = blockIdx.y * 32;
    const int tx = threadIdx.x;
    const int ty = threadIdx.y;     // 0..7
#pragma unroll
    for (int i = 0; i < 4; i++) {
        const int sr = ty * 4 + i;
        tile[sr][tx] = v[(((size_t)bh * S_) + s0 + sr) * HD_ + d0 + tx];
    }
    __syncthreads();
#pragma unroll
    for (int i = 0; i < 4; i++) {
        const int dr = ty * 4 + i;
        const float val = tile[tx][dr];
        const __nv_bfloat16 hi = __float2bfloat16_rn(val);
        const size_t o = (((size_t)bh * HD_) + d0 + dr) * S_ + s0 + tx;
        vth[o] = hi;
        vtl[o] = __float2bfloat16_rn(val - __bfloat162float(hi));
    }
}

// ---------------------------------------------------------------------------
// Flash attention on tensor cores (bf16 hi/lo 3-term splits, fp32 softmax).
// 64 q-rows per CTA, 4 warps (each m16), 64-kv tiles, HD=128.
// smem: QH/QL/KH/KL rows [row][d] pad 136; VTH/VTL rows [d][kv] pad 72.
// ---------------------------------------------------------------------------
#define FS_QH 0
#define FS_QL 17408
#define FS_KH 34816
#define FS_KL 52224
#define FS_VH 69632
#define FS_VL 88064
#define FSMEM_TOTAL 106496

__global__ __launch_bounds__(128, 2)
void flash_mma(const __nv_bfloat16* __restrict__ qh_g, const __nv_bfloat16* __restrict__ ql_g,
               const __nv_bfloat16* __restrict__ kh_g, const __nv_bfloat16* __restrict__ kl_g,
               const __nv_bfloat16* __restrict__ vth_g, const __nv_bfloat16* __restrict__ vtl_g,
               float* __restrict__ ctx)
{
    extern __shared__ char fsm[];
    const unsigned int sb = (unsigned int)__cvta_generic_to_shared(fsm);
    const int tid  = threadIdx.x;
    const int lane = tid & 31;
    const int w    = tid >> 5;
    const int qt   = blockIdx.x;    // 0..31
    const int bh   = blockIdx.y;    // 0..31

    // preload Q tiles (hi + lo)
    {
        const size_t qoff = (((size_t)bh * S_) + qt * 64) * HD_;
#pragma unroll
        for (int i = 0; i < 8; i++) {
            const int idx = tid + i * 128;
            const int row = idx >> 4, c = idx & 15;
            const unsigned int off = (unsigned int)(row * 136 + c * 8) * 2;
            cpasync16(sb + FS_QH + off, qh_g + qoff + (size_t)row * HD_ + c * 8);
            cpasync16(sb + FS_QL + off, ql_g + qoff + (size_t)row * HD_ + c * 8);
        }
        cp_commit();
    }

    float oacc[16][4];
#pragma unroll
    for (int ni = 0; ni < 16; ni++)
#pragma unroll
        for (int e = 0; e < 4; e++) oacc[ni][e] = 0.0f;
    float m_i[2] = {-3.0e30f, -3.0e30f};
    float l_i[2] = {0.0f, 0.0f};

    const float SCALE = 0.08838834764831845f;   // 1/sqrt(128)

    for (int j = 0; j <= qt; j++) {
        // load K (hi/lo) and Vt (hi/lo) tiles
        {
            const size_t koff = (((size_t)bh * S_) + j * 64) * HD_;
            const size_t voff = ((size_t)bh * HD_) * S_ + j * 64;
#pragma unroll
            for (int i = 0; i < 8; i++) {
                const int idx = tid + i * 128;
                const int r16 = idx >> 4, c16 = idx & 15;
                const unsigned int offk = (unsigned int)(r16 * 136 + c16 * 8) * 2;
                cpasync16(sb + FS_KH + offk, kh_g + koff + (size_t)r16 * HD_ + c16 * 8);
                cpasync16(sb + FS_KL + offk, kl_g + koff + (size_t)r16 * HD_ + c16 * 8);
                const int r8 = idx >> 3, c8 = idx & 7;
                const unsigned int offv = (unsigned int)(r8 * 72 + c8 * 8) * 2;
                cpasync16(sb + FS_VH + offv, vth_g + voff + (size_t)r8 * S_ + c8 * 8);
                cpasync16(sb + FS_VL + offv, vtl_g + voff + (size_t)r8 * S_ + c8 * 8);
            }
            cp_commit();
        }
        asm volatile("cp.async.wait_group 0;\n");
        __syncthreads();

        // ---- scores: S = Qh·Kh^T + Ql·Kh^T + Qh·Kl^T ----
        float sreg[8][4];
#pragma unroll
        for (int ni = 0; ni < 8; ni++)
#pragma unroll
            for (int e = 0; e < 4; e++) sreg[ni][e] = 0.0f;

#pragma unroll
        for (int kt = 0; kt < 8; kt++) {
            unsigned int qfh[4], qfl[4], bfh[8][2], bfl[8][2];
            const int arow = w * 16 + (lane & 15);
            const unsigned int aoff = (unsigned int)(arow * 136 + kt * 16 + (lane >> 4) * 8) * 2;
            ldm_x4(qfh[0], qfh[1], qfh[2], qfh[3], sb + FS_QH + aoff);
            ldm_x4(qfl[0], qfl[1], qfl[2], qfl[3], sb + FS_QL + aoff);
#pragma unroll
            for (int p = 0; p < 4; p++) {
                const int nrow = p * 16 + (lane & 7) + ((lane >> 4) << 3);
                const unsigned int boff =
                    (unsigned int)(nrow * 136 + kt * 16 + ((lane >> 3) & 1) * 8) * 2;
                ldm_x4(bfh[2*p][0], bfh[2*p][1], bfh[2*p+1][0], bfh[2*p+1][1], sb + FS_KH + boff);
                ldm_x4(bfl[2*p][0], bfl[2*p][1], bfl[2*p+1][0], bfl[2*p+1][1], sb + FS_KL + boff);
            }
#pragma unroll
            for (int ni = 0; ni < 8; ni++) mma_bf16(sreg[ni], qfh, bfh[ni]);
#pragma unroll
            for (int ni = 0; ni < 8; ni++) mma_bf16(sreg[ni], qfl, bfh[ni]);
#pragma unroll
            for (int ni = 0; ni < 8; ni++) mma_bf16(sreg[ni], qfh, bfl[ni]);
        }

        // ---- scale + causal mask ----
        const bool diag = (j == qt);
        const int r0 = lane >> 2;
        const int c0 = (lane & 3) << 1;
#pragma unroll
        for (int ni = 0; ni < 8; ni++)
#pragma unroll
            for (int e = 0; e < 4; e++) {
                sreg[ni][e] *= SCALE;
                if (diag) {
                    const int qrow = w * 16 + r0 + ((e >> 1) << 3);
                    const int kcol = ni * 8 + c0 + (e & 1);
                    if (kcol > qrow) sreg[ni][e] = -1.0e30f;
                }
            }

        // ---- online softmax (rows r0 and r0+8) ----
        float corr[2];
#pragma unroll
        for (int h2 = 0; h2 < 2; h2++) {
            const int e0 = h2 * 2;
            float mloc = -3.0e30f;
#pragma unroll
            for (int ni = 0; ni < 8; ni++)
                mloc = fmaxf(mloc, fmaxf(sreg[ni][e0], sreg[ni][e0 + 1]));
            mloc = fmaxf(mloc, __shfl_xor_sync(0xffffffffu, mloc, 1));
            mloc = fmaxf(mloc, __shfl_xor_sync(0xffffffffu, mloc, 2));
            const float mnew = fmaxf(m_i[h2], mloc);
            corr[h2] = __expf(m_i[h2] - mnew);
            m_i[h2] = mnew;
            float lloc = 0.0f;
#pragma unroll
            for (int ni = 0; ni < 8; ni++) {
                const float p0 = __expf(sreg[ni][e0]     - mnew);
                const float p1 = __expf(sreg[ni][e0 + 1] - mnew);
                sreg[ni][e0] = p0; sreg[ni][e0 + 1] = p1;
                lloc += p0 + p1;
            }
            lloc += __shfl_xor_sync(0xffffffffu, lloc, 1);
            lloc += __shfl_xor_sync(0xffffffffu, lloc, 2);
            l_i[h2] = l_i[h2] * corr[h2] + lloc;
        }
#pragma unroll
        for (int ni = 0; ni < 16; ni++)
#pragma unroll
            for (int e = 0; e < 4; e++) oacc[ni][e] *= corr[e >> 1];

        // ---- repack P into A-fragments (hi/lo) ----
        unsigned int pah[4][4], pal[4][4];
#pragma unroll
        for (int t = 0; t < 4; t++) {
#pragma unroll
            for (int rix = 0; rix < 4; rix++) {
                // rix 0: (sreg[2t][0],[1])  1: (sreg[2t][2],[3])
                // rix 2: (sreg[2t+1][0],[1]) 3: (sreg[2t+1][2],[3])
                const int ni = 2 * t + (rix >> 1);
                const int eb = (rix & 1) * 2;
                const float v0 = sreg[ni][eb], v1 = sreg[ni][eb + 1];
                const __nv_bfloat16 h0 = __float2bfloat16_rn(v0);
                const __nv_bfloat16 h1 = __float2bfloat16_rn(v1);
                const __nv_bfloat16 g0 = __float2bfloat16_rn(v0 - __bfloat162float(h0));
                const __nv_bfloat16 g1 = __float2bfloat16_rn(v1 - __bfloat162float(h1));
                pah[t][rix] = ((unsigned int)__bfloat16_as_ushort(h1) << 16) |
                              __bfloat16_as_ushort(h0);
                pal[t][rix] = ((unsigned int)__bfloat16_as_ushort(g1) << 16) |
                              __bfloat16_as_ushort(g0);
            }
        }

        // ---- O += Ph·Vh + Pl·Vh + Ph·Vl ----
#pragma unroll
        for (int t = 0; t < 4; t++) {
            unsigned int bvh[16][2], bvl[16][2];
#pragma unroll
            for (int p = 0; p < 8; p++) {
                const int nrow = p * 16 + (lane & 7) + ((lane >> 4) << 3);
                const unsigned int boff =
                    (unsigned int)(nrow * 72 + t * 16 + ((lane >> 3) & 1) * 8) * 2;
                ldm_x4(bvh[2*p][0], bvh[2*p][1], bvh[2*p+1][0], bvh[2*p+1][1], sb + FS_VH + boff);
                ldm_x4(bvl[2*p][0], bvl[2*p][1], bvl[2*p+1][0], bvl[2*p+1][1], sb + FS_VL + boff);
            }
#pragma unroll
            for (int ni = 0; ni < 16; ni++) mma_bf16(oacc[ni], pah[t], bvh[ni]);
#pragma unroll
            for (int ni = 0; ni < 16; ni++) mma_bf16(oacc[ni], pal[t], bvh[ni]);
#pragma unroll
            for (int ni = 0; ni < 16; ni++) mma_bf16(oacc[ni], pah[t], bvl[ni]);
        }
        __syncthreads();   // before next j overwrites K/V smem
    }

    // ---- epilogue ----
    const float linv0 = 1.0f / l_i[0];
    const float linv1 = 1.0f / l_i[1];
    const int b = bh >> 4;
    const int h = bh & (NH_ - 1);
#pragma unroll
    for (int ni = 0; ni < 16; ni++) {
#pragma unroll
        for (int e = 0; e < 4; e++) {
            const int qrow = qt * 64 + w * 16 + (lane >> 2) + ((e >> 1) << 3);
            const int d = ni * 8 + ((lane & 3) << 1) + (e & 1);
            ctx[(((size_t)(b * S_ + qrow)) * NH_ + h) * HD_ + d] =
                oacc[ni][e] * ((e < 2) ? linv0 : linv1);
        }
    }
}

// ---------------------------------------------------------------------------
extern "C" void kernel_launch(void* const* d_in, const int* in_sizes, int n_in,
                              void* d_out, int out_size)
{
    const float* hs  = (const float*)d_in[0];
    // d_in[1] = attention_mask: deterministically causal, applied analytically
    const int*   pos = (const int*)d_in[2];
    const float* Wq  = (const float*)d_in[3];
    const float* Wk  = (const float*)d_in[4];
    const float* Wv  = (const float*)d_in[5];
    const float* Wo  = (const float*)d_in[6];
    float* out = (float*)d_out;

    float *q, *k, *v, *ctx;
    __nv_bfloat16 *aex, *cex, *wqe, *wke, *wve, *woe;
    __nv_bfloat16 *qh, *ql, *kh, *kl, *vth, *vtl;
    cudaGetSymbolAddress((void**)&q,   g_q);
    cudaGetSymbolAddress((void**)&k,   g_k);
    cudaGetSymbolAddress((void**)&v,   g_v);
    cudaGetSymbolAddress((void**)&ctx, g_ctx);
    cudaGetSymbolAddress((void**)&aex, g_aex);
    cudaGetSymbolAddress((void**)&cex, g_cex);
    cudaGetSymbolAddress((void**)&wqe, g_wqe);
    cudaGetSymbolAddress((void**)&wke, g_wke);
    cudaGetSymbolAddress((void**)&wve, g_wve);
    cudaGetSymbolAddress((void**)&woe, g_woe);
    cudaGetSymbolAddress((void**)&qh,  g_qh);
    cudaGetSymbolAddress((void**)&ql,  g_ql);
    cudaGetSymbolAddress((void**)&kh,  g_kh);
    cudaGetSymbolAddress((void**)&kl,  g_kl);
    cudaGetSymbolAddress((void**)&vth, g_vth);
    cudaGetSymbolAddress((void**)&vtl, g_vtl);

    const int nA4 = (M_ * K_) / 4;
    const int nW4 = (HID_ * K_) / 4;
    split_expand<<<(nA4 + 255) / 256, 256>>>(hs, aex, nA4, 0);
    split_expand<<<(nW4 + 255) / 256, 256>>>(Wq, wqe, nW4, 1);
    split_expand<<<(nW4 + 255) / 256, 256>>>(Wk, wke, nW4, 1);
    split_expand<<<(nW4 + 255) / 256, 256>>>(Wv, wve, nW4, 1);
    split_expand<<<(nW4 + 255) / 256, 256>>>(Wo, woe, nW4, 1);

    static bool attr_set = false;
    if (!attr_set) {
        cudaFuncSetAttribute(gemm_bf16, cudaFuncAttributeMaxDynamicSharedMemorySize, GEMM_SMEM);
        cudaFuncSetAttribute(flash_mma, cudaFuncAttributeMaxDynamicSharedMemorySize, FSMEM_TOTAL);
        attr_set = true;
    }

    const dim3 ggrid(HID_ / GBN, M_ / GBM);   // (16, 32)
    gemm_bf16<<<ggrid, 256, GEMM_SMEM>>>(aex, wqe, q, HID_, KEX_, 1);
    gemm_bf16<<<ggrid, 256, GEMM_SMEM>>>(aex, wke, k, HID_, KEX_, 1);
    gemm_bf16<<<ggrid, 256, GEMM_SMEM>>>(aex, wve, v, HID_, KEX_, 1);

    const int rope_total = B_ * NH_ * S_ * (HD_ / 2);
    rope_split<<<(rope_total + 255) / 256, 256>>>(q, k, pos, qh, ql, kh, kl);

    vsplit_t<<<dim3(S_ / 32, HD_ / 32, B_ * NH_), dim3(32, 8)>>>(v, vth, vtl);

    flash_mma<<<dim3(S_ / 64, B_ * NH_), 128, FSMEM_TOTAL>>>(qh, ql, kh, kl, vth, vtl, ctx);

    split_expand<<<(nA4 + 255) / 256, 256>>>(ctx, cex, nA4, 0);
    gemm_bf16<<<ggrid, 256, GEMM_SMEM>>>(cex, woe, out, HID_, KEX_, 0);
}

// round 8
// speedup vs baseline: 1.9327x; 1.0583x over previous
#include <cuda_runtime.h>
#include <cuda_bf16.h>
#include <cstdint>
#include <cstddef>
#include <math.h>

// Problem constants
#define B_   2
#define S_   2048
#define HID_ 2048
#define NH_  16
#define HD_  128
#define M_   (B_ * S_)     // 4096
#define K_   HID_          // 2048
#define KEX_ (3 * K_)      // 6144 expanded (hi|lo|hi split)

// ---------------------------------------------------------------------------
// Scratch (allocation-free rule: __device__ globals)
// ---------------------------------------------------------------------------
__device__ float g_q[B_ * NH_ * S_ * HD_];     // [b,h,s,d] fp32
__device__ float g_k[B_ * NH_ * S_ * HD_];
__device__ float g_v[B_ * NH_ * S_ * HD_];
__device__ float g_ctx[B_ * S_ * HID_];        // [b,s,h*HD+d] fp32

__device__ __nv_bfloat16 g_aex[(size_t)M_ * KEX_];
__device__ __nv_bfloat16 g_cex[(size_t)M_ * KEX_];
__device__ __nv_bfloat16 g_wqe[(size_t)HID_ * KEX_];
__device__ __nv_bfloat16 g_wke[(size_t)HID_ * KEX_];
__device__ __nv_bfloat16 g_wve[(size_t)HID_ * KEX_];
__device__ __nv_bfloat16 g_woe[(size_t)HID_ * KEX_];

// flash operands: hi/lo bf16
__device__ __nv_bfloat16 g_qh[B_ * NH_ * S_ * HD_];   // [b,h,s,d]
__device__ __nv_bfloat16 g_ql[B_ * NH_ * S_ * HD_];
__device__ __nv_bfloat16 g_kh[B_ * NH_ * S_ * HD_];
__device__ __nv_bfloat16 g_kl[B_ * NH_ * S_ * HD_];
__device__ __nv_bfloat16 g_vth[B_ * NH_ * S_ * HD_];  // [b,h,d,s] (transposed)
__device__ __nv_bfloat16 g_vtl[B_ * NH_ * S_ * HD_];

// ---------------------------------------------------------------------------
// fp32 -> bf16 hi/lo split, expanded-K layout (vectorized).
// ---------------------------------------------------------------------------
__global__ void split_expand(const float* __restrict__ X,
                             __nv_bfloat16* __restrict__ Y,
                             int total4, int mode)
{
    const int t = blockIdx.x * blockDim.x + threadIdx.x;
    if (t >= total4) return;
    const int idx = t * 4;
    const int r = idx >> 11;
    const int k = idx & (K_ - 1);
    const float4 x = *(const float4*)(X + idx);

    __nv_bfloat16 hi[4], lo[4];
    const float xs[4] = {x.x, x.y, x.z, x.w};
#pragma unroll
    for (int i = 0; i < 4; i++) {
        hi[i] = __float2bfloat16_rn(xs[i]);
        lo[i] = __float2bfloat16_rn(xs[i] - __bfloat162float(hi[i]));
    }
    __nv_bfloat16* dst = Y + (size_t)r * KEX_ + k;
    *(uint2*)(dst) = *(const uint2*)hi;
    if (mode == 0) {
        *(uint2*)(dst + K_)     = *(const uint2*)lo;
        *(uint2*)(dst + 2 * K_) = *(const uint2*)hi;
    } else {
        *(uint2*)(dst + K_)     = *(const uint2*)hi;
        *(uint2*)(dst + 2 * K_) = *(const uint2*)lo;
    }
}

// ---------------------------------------------------------------------------
// mma / cp.async helpers
// ---------------------------------------------------------------------------
__device__ __forceinline__ void cpasync16(unsigned int smem_dst, const void* gsrc) {
    asm volatile("cp.async.cg.shared.global [%0], [%1], 16;\n" :: "r"(smem_dst), "l"(gsrc));
}
__device__ __forceinline__ void cp_commit() {
    asm volatile("cp.async.commit_group;\n");
}
__device__ __forceinline__ void ldm_x4(unsigned int& r0, unsigned int& r1,
                                       unsigned int& r2, unsigned int& r3,
                                       unsigned int addr) {
    asm volatile("ldmatrix.sync.aligned.m8n8.x4.shared.b16 {%0,%1,%2,%3}, [%4];\n"
                 : "=r"(r0), "=r"(r1), "=r"(r2), "=r"(r3) : "r"(addr));
}
__device__ __forceinline__ void mma_bf16(float* c, const unsigned int* a,
                                         const unsigned int* b) {
    asm volatile(
        "mma.sync.aligned.m16n8k16.row.col.f32.bf16.bf16.f32 "
        "{%0,%1,%2,%3}, {%4,%5,%6,%7}, {%8,%9}, {%0,%1,%2,%3};\n"
        : "+f"(c[0]), "+f"(c[1]), "+f"(c[2]), "+f"(c[3])
        : "r"(a[0]), "r"(a[1]), "r"(a[2]), "r"(a[3]), "r"(b[0]), "r"(b[1]));
}

// ---------------------------------------------------------------------------
// GEMM configuration (proven R5/R7 shape)
// ---------------------------------------------------------------------------
#define GBM 128
#define GBN 128
#define GBK 64
#define LDP 72
#define GSTG 3
#define STG_B (GBM * LDP * 2)
#define GEMM_SMEM (2 * GSTG * STG_B)

// ---------------------------------------------------------------------------
// Fused QKV GEMM: one launch, grid (48, 32). n-block selects weight + dest.
// C_sel[b,h,s,d] scatter (layout-1 of the original).
// ---------------------------------------------------------------------------
__global__ __launch_bounds__(256, 2)
void gemm_qkv(const __nv_bfloat16* __restrict__ A,
              const __nv_bfloat16* __restrict__ Wq,
              const __nv_bfloat16* __restrict__ Wk,
              const __nv_bfloat16* __restrict__ Wv,
              float* __restrict__ Cq, float* __restrict__ Ck,
              float* __restrict__ Cv)
{
    extern __shared__ char gsm[];
    const unsigned int sbase = (unsigned int)__cvta_generic_to_shared(gsm);
    const unsigned int sBoff = GSTG * STG_B;

    const int tid  = threadIdx.x;
    const int lane = tid & 31;
    const int w    = tid >> 5;
    const int wm   = (w >> 1) << 5;
    const int wn   = (w & 1) << 6;
    const int m0   = blockIdx.y * GBM;
    const int ng   = blockIdx.x * GBN;          // 0..6143
    const int which = ng >> 11;                 // 0=q,1=k,2=v
    const int n0   = ng & (K_ - 1);             // within-matrix n base

    const __nv_bfloat16* W = (which == 0) ? Wq : (which == 1) ? Wk : Wv;
    float* C = (which == 0) ? Cq : (which == 1) ? Ck : Cv;

    float acc[2][8][4];
#pragma unroll
    for (int mi = 0; mi < 2; mi++)
#pragma unroll
        for (int ni = 0; ni < 8; ni++)
#pragma unroll
            for (int e = 0; e < 4; e++) acc[mi][ni][e] = 0.0f;

    const int lr = tid >> 3;
    const int lc = tid & 7;
    const int NT = KEX_ / GBK;

    auto load_stage = [&](int kt, int s) {
        const unsigned int aD = sbase + s * STG_B;
        const unsigned int bD = sbase + sBoff + s * STG_B;
        const __nv_bfloat16* Ap = A + (size_t)m0 * KEX_ + kt * GBK + lc * 8;
        const __nv_bfloat16* Wp = W + (size_t)n0 * KEX_ + kt * GBK + lc * 8;
#pragma unroll
        for (int i = 0; i < 4; i++) {
            const int row = lr + i * 32;
            const unsigned int off = (unsigned int)(row * LDP + lc * 8) * 2;
            cpasync16(aD + off, Ap + (size_t)row * KEX_);
            cpasync16(bD + off, Wp + (size_t)row * KEX_);
        }
        cp_commit();
    };

    load_stage(0, 0);
    load_stage(1, 1);

    for (int kt = 0; kt < NT; kt++) {
        if (kt + 1 < NT) {
            asm volatile("cp.async.wait_group 1;\n");
        } else {
            asm volatile("cp.async.wait_group 0;\n");
        }
        __syncthreads();

        if (kt + 2 < NT) load_stage(kt + 2, (kt + 2) % GSTG);

        const int s = kt % GSTG;
        const unsigned int aBase = sbase + s * STG_B;
        const unsigned int bBase = sbase + sBoff + s * STG_B;

#pragma unroll
        for (int ks = 0; ks < 4; ks++) {
            unsigned int afr[2][4], bfr[8][2];
#pragma unroll
            for (int mi = 0; mi < 2; mi++) {
                const int row = wm + mi * 16 + (lane & 15);
                const unsigned int addr =
                    aBase + (unsigned int)(row * LDP + ks * 16 + (lane >> 4) * 8) * 2;
                ldm_x4(afr[mi][0], afr[mi][1], afr[mi][2], afr[mi][3], addr);
            }
#pragma unroll
            for (int p = 0; p < 4; p++) {
                const int nrow = wn + p * 16 + (lane & 7) + ((lane >> 4) << 3);
                const int chunk = (lane >> 3) & 1;
                const unsigned int addr =
                    bBase + (unsigned int)(nrow * LDP + ks * 16 + chunk * 8) * 2;
                ldm_x4(bfr[2 * p][0], bfr[2 * p][1], bfr[2 * p + 1][0], bfr[2 * p + 1][1], addr);
            }
#pragma unroll
            for (int mi = 0; mi < 2; mi++)
#pragma unroll
                for (int ni = 0; ni < 8; ni++)
                    mma_bf16(acc[mi][ni], afr[mi], bfr[ni]);
        }
    }

#pragma unroll
    for (int mi = 0; mi < 2; mi++) {
#pragma unroll
        for (int ni = 0; ni < 8; ni++) {
            const int rr = m0 + wm + mi * 16 + (lane >> 2);
            const int cc = n0 + wn + ni * 8 + ((lane & 3) << 1);
#pragma unroll
            for (int e = 0; e < 4; e++) {
                const int m = rr + ((e >> 1) << 3);
                const int n = cc + (e & 1);
                const int b = m >> 11, s2 = m & (S_ - 1);
                const int h = n >> 7,  d = n & (HD_ - 1);
                C[(((size_t)(b * NH_ + h)) * S_ + s2) * HD_ + d] = acc[mi][ni][e];
            }
        }
    }
}

// ---------------------------------------------------------------------------
// Plain GEMM (used for the Wo projection, layout 0).
// ---------------------------------------------------------------------------
__global__ __launch_bounds__(256, 2)
void gemm_bf16(const __nv_bfloat16* __restrict__ A,
               const __nv_bfloat16* __restrict__ W,
               float* __restrict__ C, int N, int Kex)
{
    extern __shared__ char gsm[];
    const unsigned int sbase = (unsigned int)__cvta_generic_to_shared(gsm);
    const unsigned int sBoff = GSTG * STG_B;

    const int tid  = threadIdx.x;
    const int lane = tid & 31;
    const int w    = tid >> 5;
    const int wm   = (w >> 1) << 5;
    const int wn   = (w & 1) << 6;
    const int m0   = blockIdx.y * GBM;
    const int n0   = blockIdx.x * GBN;

    float acc[2][8][4];
#pragma unroll
    for (int mi = 0; mi < 2; mi++)
#pragma unroll
        for (int ni = 0; ni < 8; ni++)
#pragma unroll
            for (int e = 0; e < 4; e++) acc[mi][ni][e] = 0.0f;

    const int lr = tid >> 3;
    const int lc = tid & 7;
    const int NT = Kex / GBK;

    auto load_stage = [&](int kt, int s) {
        const unsigned int aD = sbase + s * STG_B;
        const unsigned int bD = sbase + sBoff + s * STG_B;
        const __nv_bfloat16* Ap = A + (size_t)m0 * Kex + kt * GBK + lc * 8;
        const __nv_bfloat16* Wp = W + (size_t)n0 * Kex + kt * GBK + lc * 8;
#pragma unroll
        for (int i = 0; i < 4; i++) {
            const int row = lr + i * 32;
            const unsigned int off = (unsigned int)(row * LDP + lc * 8) * 2;
            cpasync16(aD + off, Ap + (size_t)row * Kex);
            cpasync16(bD + off, Wp + (size_t)row * Kex);
        }
        cp_commit();
    };

    load_stage(0, 0);
    load_stage(1, 1);

    for (int kt = 0; kt < NT; kt++) {
        if (kt + 1 < NT) {
            asm volatile("cp.async.wait_group 1;\n");
        } else {
            asm volatile("cp.async.wait_group 0;\n");
        }
        __syncthreads();

        if (kt + 2 < NT) load_stage(kt + 2, (kt + 2) % GSTG);

        const int s = kt % GSTG;
        const unsigned int aBase = sbase + s * STG_B;
        const unsigned int bBase = sbase + sBoff + s * STG_B;

#pragma unroll
        for (int ks = 0; ks < 4; ks++) {
            unsigned int afr[2][4], bfr[8][2];
#pragma unroll
            for (int mi = 0; mi < 2; mi++) {
                const int row = wm + mi * 16 + (lane & 15);
                const unsigned int addr =
                    aBase + (unsigned int)(row * LDP + ks * 16 + (lane >> 4) * 8) * 2;
                ldm_x4(afr[mi][0], afr[mi][1], afr[mi][2], afr[mi][3], addr);
            }
#pragma unroll
            for (int p = 0; p < 4; p++) {
                const int nrow = wn + p * 16 + (lane & 7) + ((lane >> 4) << 3);
                const int chunk = (lane >> 3) & 1;
                const unsigned int addr =
                    bBase + (unsigned int)(nrow * LDP + ks * 16 + chunk * 8) * 2;
                ldm_x4(bfr[2 * p][0], bfr[2 * p][1], bfr[2 * p + 1][0], bfr[2 * p + 1][1], addr);
            }
#pragma unroll
            for (int mi = 0; mi < 2; mi++)
#pragma unroll
                for (int ni = 0; ni < 8; ni++)
                    mma_bf16(acc[mi][ni], afr[mi], bfr[ni]);
        }
    }

#pragma unroll
    for (int mi = 0; mi < 2; mi++) {
#pragma unroll
        for (int ni = 0; ni < 8; ni++) {
            const int rr = m0 + wm + mi * 16 + (lane >> 2);
            const int cc = n0 + wn + ni * 8 + ((lane & 3) << 1);
#pragma unroll
            for (int e = 0; e < 4; e++) {
                const int m = rr + ((e >> 1) << 3);
                const int n = cc + (e & 1);
                C[(size_t)m * N + n] = acc[mi][ni][e];
            }
        }
    }
}

// ---------------------------------------------------------------------------
// RoPE + hi/lo split:  fp32 q,k -> qh/ql/kh/kl bf16 ([b,h,s,d]).
// ---------------------------------------------------------------------------
__global__ void rope_split(const float* __restrict__ q, const float* __restrict__ k,
                           const int* __restrict__ pos_ids,
                           __nv_bfloat16* __restrict__ qh, __nv_bfloat16* __restrict__ ql,
                           __nv_bfloat16* __restrict__ kh, __nv_bfloat16* __restrict__ kl)
{
    const int idx = blockIdx.x * blockDim.x + threadIdx.x;
    const int total = B_ * NH_ * S_ * (HD_ / 2);
    if (idx >= total) return;
    const int d = idx & 63;
    int t = idx >> 6;
    const int s = t & (S_ - 1);
    t >>= 11;
    const int h = t & (NH_ - 1);
    const int b = t >> 4;

    const int p = pos_ids[b * S_ + s];
    const float e = (float)(-(2 * d)) * 0.10381025296523008f;
    const float inv_f = exp2f(e);
    const float ang = (float)p * inv_f;
    float sn, cs;
    sincosf(ang, &sn, &cs);

    const size_t base = (((size_t)(b * NH_ + h)) * S_ + s) * HD_ + d;
    const float q1 = q[base], q2 = q[base + 64];
    const float k1 = k[base], k2 = k[base + 64];
    const float rq1 = q1 * cs - q2 * sn, rq2 = q2 * cs + q1 * sn;
    const float rk1 = k1 * cs - k2 * sn, rk2 = k2 * cs + k1 * sn;

    __nv_bfloat16 hv;
    hv = __float2bfloat16_rn(rq1); qh[base]    = hv; ql[base]    = __float2bfloat16_rn(rq1 - __bfloat162float(hv));
    hv = __float2bfloat16_rn(rq2); qh[base+64] = hv; ql[base+64] = __float2bfloat16_rn(rq2 - __bfloat162float(hv));
    hv = __float2bfloat16_rn(rk1); kh[base]    = hv; kl[base]    = __float2bfloat16_rn(rk1 - __bfloat162float(hv));
    hv = __float2bfloat16_rn(rk2); kh[base+64] = hv; kl[base+64] = __float2bfloat16_rn(rk2 - __bfloat162float(hv));
}

// ---------------------------------------------------------------------------
// V transpose + split: g_v [bh][s][d] fp32 -> vth/vtl [bh][d][s] bf16.
// ---------------------------------------------------------------------------
__global__ void vsplit_t(const float* __restrict__ v,
                         __nv_bfloat16* __restrict__ vth,
                         __nv_bfloat16* __restrict__ vtl)
{
    __shared__ float tile[32][33];
    const int bh = blockIdx.z;
    const int s0 = blockIdx.x * 32;
    const int d0 = blockIdx.y * 32;
    const int tx = threadIdx.x;
    const int ty = threadIdx.y;     // 0..7
#pragma unroll
    for (int i = 0; i < 4; i++) {
        const int sr = ty * 4 + i;
        tile[sr][tx] = v[(((size_t)bh * S_) + s0 + sr) * HD_ + d0 + tx];
    }
    __syncthreads();
#pragma unroll
    for (int i = 0; i < 4; i++) {
        const int dr = ty * 4 + i;
        const float val = tile[tx][dr];
        const __nv_bfloat16 hi = __float2bfloat16_rn(val);
        const size_t o = (((size_t)bh * HD_) + d0 + dr) * S_ + s0 + tx;
        vth[o] = hi;
        vtl[o] = __float2bfloat16_rn(val - __bfloat162float(hi));
    }
}

// ---------------------------------------------------------------------------
// Flash attention on tensor cores (bf16 hi/lo 3-term splits, fp32 softmax).
// 64 q-rows per CTA, 4 warps, 64-kv tiles, HD=128.
// Longest-first scheduling: qt = 31 - blockIdx.x (LPT makespan).
// ---------------------------------------------------------------------------
#define FS_QH 0
#define FS_QL 17408
#define FS_KH 34816
#define FS_KL 52224
#define FS_VH 69632
#define FS_VL 88064
#define FSMEM_TOTAL 106496

__global__ __launch_bounds__(128, 2)
void flash_mma(const __nv_bfloat16* __restrict__ qh_g, const __nv_bfloat16* __restrict__ ql_g,
               const __nv_bfloat16* __restrict__ kh_g, const __nv_bfloat16* __restrict__ kl_g,
               const __nv_bfloat16* __restrict__ vth_g, const __nv_bfloat16* __restrict__ vtl_g,
               float* __restrict__ ctx)
{
    extern __shared__ char fsm[];
    const unsigned int sb = (unsigned int)__cvta_generic_to_shared(fsm);
    const int tid  = threadIdx.x;
    const int lane = tid & 31;
    const int w    = tid >> 5;
    const int qt   = (S_ / 64 - 1) - blockIdx.x;   // longest-first (LPT)
    const int bh   = blockIdx.y;

    // preload Q tiles (hi + lo)
    {
        const size_t qoff = (((size_t)bh * S_) + qt * 64) * HD_;
#pragma unroll
        for (int i = 0; i < 8; i++) {
            const int idx = tid + i * 128;
            const int row = idx >> 4, c = idx & 15;
            const unsigned int off = (unsigned int)(row * 136 + c * 8) * 2;
            cpasync16(sb + FS_QH + off, qh_g + qoff + (size_t)row * HD_ + c * 8);
            cpasync16(sb + FS_QL + off, ql_g + qoff + (size_t)row * HD_ + c * 8);
        }
        cp_commit();
    }

    float oacc[16][4];
#pragma unroll
    for (int ni = 0; ni < 16; ni++)
#pragma unroll
        for (int e = 0; e < 4; e++) oacc[ni][e] = 0.0f;
    float m_i[2] = {-3.0e30f, -3.0e30f};
    float l_i[2] = {0.0f, 0.0f};

    const float SCALE = 0.08838834764831845f;   // 1/sqrt(128)

    for (int j = 0; j <= qt; j++) {
        // load K (hi/lo) and Vt (hi/lo) tiles
        {
            const size_t koff = (((size_t)bh * S_) + j * 64) * HD_;
            const size_t voff = ((size_t)bh * HD_) * S_ + j * 64;
#pragma unroll
            for (int i = 0; i < 8; i++) {
                const int idx = tid + i * 128;
                const int r16 = idx >> 4, c16 = idx & 15;
                const unsigned int offk = (unsigned int)(r16 * 136 + c16 * 8) * 2;
                cpasync16(sb + FS_KH + offk, kh_g + koff + (size_t)r16 * HD_ + c16 * 8);
                cpasync16(sb + FS_KL + offk, kl_g + koff + (size_t)r16 * HD_ + c16 * 8);
                const int r8 = idx >> 3, c8 = idx & 7;
                const unsigned int offv = (unsigned int)(r8 * 72 + c8 * 8) * 2;
                cpasync16(sb + FS_VH + offv, vth_g + voff + (size_t)r8 * S_ + c8 * 8);
                cpasync16(sb + FS_VL + offv, vtl_g + voff + (size_t)r8 * S_ + c8 * 8);
            }
            cp_commit();
        }
        asm volatile("cp.async.wait_group 0;\n");
        __syncthreads();

        // ---- scores: S = Qh·Kh^T + Ql·Kh^T + Qh·Kl^T ----
        float sreg[8][4];
#pragma unroll
        for (int ni = 0; ni < 8; ni++)
#pragma unroll
            for (int e = 0; e < 4; e++) sreg[ni][e] = 0.0f;

#pragma unroll
        for (int kt = 0; kt < 8; kt++) {
            unsigned int qfh[4], qfl[4], bfh[8][2], bfl[8][2];
            const int arow = w * 16 + (lane & 15);
            const unsigned int aoff = (unsigned int)(arow * 136 + kt * 16 + (lane >> 4) * 8) * 2;
            ldm_x4(qfh[0], qfh[1], qfh[2], qfh[3], sb + FS_QH + aoff);
            ldm_x4(qfl[0], qfl[1], qfl[2], qfl[3], sb + FS_QL + aoff);
#pragma unroll
            for (int p = 0; p < 4; p++) {
                const int nrow = p * 16 + (lane & 7) + ((lane >> 4) << 3);
                const unsigned int boff =
                    (unsigned int)(nrow * 136 + kt * 16 + ((lane >> 3) & 1) * 8) * 2;
                ldm_x4(bfh[2*p][0], bfh[2*p][1], bfh[2*p+1][0], bfh[2*p+1][1], sb + FS_KH + boff);
                ldm_x4(bfl[2*p][0], bfl[2*p][1], bfl[2*p+1][0], bfl[2*p+1][1], sb + FS_KL + boff);
            }
#pragma unroll
            for (int ni = 0; ni < 8; ni++) mma_bf16(sreg[ni], qfh, bfh[ni]);
#pragma unroll
            for (int ni = 0; ni < 8; ni++) mma_bf16(sreg[ni], qfl, bfh[ni]);
#pragma unroll
            for (int ni = 0; ni < 8; ni++) mma_bf16(sreg[ni], qfh, bfl[ni]);
        }

        // ---- scale + causal mask ----
        const bool diag = (j == qt);
        const int r0 = lane >> 2;
        const int c0 = (lane & 3) << 1;
#pragma unroll
        for (int ni = 0; ni < 8; ni++)
#pragma unroll
            for (int e = 0; e < 4; e++) {
                sreg[ni][e] *= SCALE;
                if (diag) {
                    const int qrow = w * 16 + r0 + ((e >> 1) << 3);
                    const int kcol = ni * 8 + c0 + (e & 1);
                    if (kcol > qrow) sreg[ni][e] = -1.0e30f;
                }
            }

        // ---- online softmax (rows r0 and r0+8) ----
        float corr[2];
#pragma unroll
        for (int h2 = 0; h2 < 2; h2++) {
            const int e0 = h2 * 2;
            float mloc = -3.0e30f;
#pragma unroll
            for (int ni = 0; ni < 8; ni++)
                mloc = fmaxf(mloc, fmaxf(sreg[ni][e0], sreg[ni][e0 + 1]));
            mloc = fmaxf(mloc, __shfl_xor_sync(0xffffffffu, mloc, 1));
            mloc = fmaxf(mloc, __shfl_xor_sync(0xffffffffu, mloc, 2));
            const float mnew = fmaxf(m_i[h2], mloc);
            corr[h2] = __expf(m_i[h2] - mnew);
            m_i[h2] = mnew;
            float lloc = 0.0f;
#pragma unroll
            for (int ni = 0; ni < 8; ni++) {
                const float p0 = __expf(sreg[ni][e0]     - mnew);
                const float p1 = __expf(sreg[ni][e0 + 1] - mnew);
                sreg[ni][e0] = p0; sreg[ni][e0 + 1] = p1;
                lloc += p0 + p1;
            }
            lloc += __shfl_xor_sync(0xffffffffu, lloc, 1);
            lloc += __shfl_xor_sync(0xffffffffu, lloc, 2);
            l_i[h2] = l_i[h2] * corr[h2] + lloc;
        }
#pragma unroll
        for (int ni = 0; ni < 16; ni++)
#pragma unroll
            for (int e = 0; e < 4; e++) oacc[ni][e] *= corr[e >> 1];

        // ---- repack P into A-fragments (hi/lo) ----
        unsigned int pah[4][4], pal[4][4];
#pragma unroll
        for (int t = 0; t < 4; t++) {
#pragma unroll
            for (int rix = 0; rix < 4; rix++) {
                const int ni = 2 * t + (rix >> 1);
                const int eb = (rix & 1) * 2;
                const float v0 = sreg[ni][eb], v1 = sreg[ni][eb + 1];
                const __nv_bfloat16 h0 = __float2bfloat16_rn(v0);
                const __nv_bfloat16 h1 = __float2bfloat16_rn(v1);
                const __nv_bfloat16 g0 = __float2bfloat16_rn(v0 - __bfloat162float(h0));
                const __nv_bfloat16 g1 = __float2bfloat16_rn(v1 - __bfloat162float(h1));
                pah[t][rix] = ((unsigned int)__bfloat16_as_ushort(h1) << 16) |
                              __bfloat16_as_ushort(h0);
                pal[t][rix] = ((unsigned int)__bfloat16_as_ushort(g1) << 16) |
                              __bfloat16_as_ushort(g0);
            }
        }

        // ---- O += Ph·Vh + Pl·Vh + Ph·Vl ----
#pragma unroll
        for (int t = 0; t < 4; t++) {
            unsigned int bvh[16][2], bvl[16][2];
#pragma unroll
            for (int p = 0; p < 8; p++) {
                const int nrow = p * 16 + (lane & 7) + ((lane >> 4) << 3);
                const unsigned int boff =
                    (unsigned int)(nrow * 72 + t * 16 + ((lane >> 3) & 1) * 8) * 2;
                ldm_x4(bvh[2*p][0], bvh[2*p][1], bvh[2*p+1][0], bvh[2*p+1][1], sb + FS_VH + boff);
                ldm_x4(bvl[2*p][0], bvl[2*p][1], bvl[2*p+1][0], bvl[2*p+1][1], sb + FS_VL + boff);
            }
#pragma unroll
            for (int ni = 0; ni < 16; ni++) mma_bf16(oacc[ni], pah[t], bvh[ni]);
#pragma unroll
            for (int ni = 0; ni < 16; ni++) mma_bf16(oacc[ni], pal[t], bvh[ni]);
#pragma unroll
            for (int ni = 0; ni < 16; ni++) mma_bf16(oacc[ni], pah[t], bvl[ni]);
        }
        __syncthreads();   // before next j overwrites K/V smem
    }

    // ---- epilogue ----
    const float linv0 = 1.0f / l_i[0];
    const float linv1 = 1.0f / l_i[1];
    const int b = bh >> 4;
    const int h = bh & (NH_ - 1);
#pragma unroll
    for (int ni = 0; ni < 16; ni++) {
#pragma unroll
        for (int e = 0; e < 4; e++) {
            const int qrow = qt * 64 + w * 16 + (lane >> 2) + ((e >> 1) << 3);
            const int d = ni * 8 + ((lane & 3) << 1) + (e & 1);
            ctx[(((size_t)(b * S_ + qrow)) * NH_ + h) * HD_ + d] =
                oacc[ni][e] * ((e < 2) ? linv0 : linv1);
        }
    }
}

// ---------------------------------------------------------------------------
extern "C" void kernel_launch(void* const* d_in, const int* in_sizes, int n_in,
                              void* d_out, int out_size)
{
    const float* hs  = (const float*)d_in[0];
    // d_in[1] = attention_mask: deterministically causal, applied analytically
    const int*   pos = (const int*)d_in[2];
    const float* Wq  = (const float*)d_in[3];
    const float* Wk  = (const float*)d_in[4];
    const float* Wv  = (const float*)d_in[5];
    const float* Wo  = (const float*)d_in[6];
    float* out = (float*)d_out;

    float *q, *k, *v, *ctx;
    __nv_bfloat16 *aex, *cex, *wqe, *wke, *wve, *woe;
    __nv_bfloat16 *qh, *ql, *kh, *kl, *vth, *vtl;
    cudaGetSymbolAddress((void**)&q,   g_q);
    cudaGetSymbolAddress((void**)&k,   g_k);
    cudaGetSymbolAddress((void**)&v,   g_v);
    cudaGetSymbolAddress((void**)&ctx, g_ctx);
    cudaGetSymbolAddress((void**)&aex, g_aex);
    cudaGetSymbolAddress((void**)&cex, g_cex);
    cudaGetSymbolAddress((void**)&wqe, g_wqe);
    cudaGetSymbolAddress((void**)&wke, g_wke);
    cudaGetSymbolAddress((void**)&wve, g_wve);
    cudaGetSymbolAddress((void**)&woe, g_woe);
    cudaGetSymbolAddress((void**)&qh,  g_qh);
    cudaGetSymbolAddress((void**)&ql,  g_ql);
    cudaGetSymbolAddress((void**)&kh,  g_kh);
    cudaGetSymbolAddress((void**)&kl,  g_kl);
    cudaGetSymbolAddress((void**)&vth, g_vth);
    cudaGetSymbolAddress((void**)&vtl, g_vtl);

    const int nA4 = (M_ * K_) / 4;
    const int nW4 = (HID_ * K_) / 4;
    split_expand<<<(nA4 + 255) / 256, 256>>>(hs, aex, nA4, 0);
    split_expand<<<(nW4 + 255) / 256, 256>>>(Wq, wqe, nW4, 1);
    split_expand<<<(nW4 + 255) / 256, 256>>>(Wk, wke, nW4, 1);
    split_expand<<<(nW4 + 255) / 256, 256>>>(Wv, wve, nW4, 1);
    split_expand<<<(nW4 + 255) / 256, 256>>>(Wo, woe, nW4, 1);

    static bool attr_set = false;
    if (!attr_set) {
        cudaFuncSetAttribute(gemm_qkv,  cudaFuncAttributeMaxDynamicSharedMemorySize, GEMM_SMEM);
        cudaFuncSetAttribute(gemm_bf16, cudaFuncAttributeMaxDynamicSharedMemorySize, GEMM_SMEM);
        cudaFuncSetAttribute(flash_mma, cudaFuncAttributeMaxDynamicSharedMemorySize, FSMEM_TOTAL);
        attr_set = true;
    }

    // fused QKV projection: one launch, grid (48, 32)
    gemm_qkv<<<dim3(3 * HID_ / GBN, M_ / GBM), 256, GEMM_SMEM>>>(
        aex, wqe, wke, wve, q, k, v);

    const int rope_total = B_ * NH_ * S_ * (HD_ / 2);
    rope_split<<<(rope_total + 255) / 256, 256>>>(q, k, pos, qh, ql, kh, kl);

    vsplit_t<<<dim3(S_ / 32, HD_ / 32, B_ * NH_), dim3(32, 8)>>>(v, vth, vtl);

    flash_mma<<<dim3(S_ / 64, B_ * NH_), 128, FSMEM_TOTAL>>>(qh, ql, kh, kl, vth, vtl, ctx);

    split_expand<<<(nA4 + 255) / 256, 256>>>(ctx, cex, nA4, 0);
    gemm_bf16<<<dim3(HID_ / GBN, M_ / GBM), 256, GEMM_SMEM>>>(cex, woe, out, HID_, KEX_);
}